// round 6
// baseline (speedup 1.0000x reference)
#include <cuda_runtime.h>
#include <cuda_bf16.h>
#include <cstdint>

#define CD 1280
#define RD 4
#define BB 2
#define SS 2048
#define MM 4096
#define HH 20
#define DD 64
#define NQKV 3840

// ---------------- device scratch (bf16 hi/lo split operands) ----------------
__device__ __nv_bfloat16 g_x_h[MM * CD],    g_x_l[MM * CD];
__device__ __nv_bfloat16 g_W_h[NQKV * CD],  g_W_l[NQKV * CD];
__device__ __nv_bfloat16 g_Wo_h[CD * CD],   g_Wo_l[CD * CD];
__device__ __nv_bfloat16 g_qkv_h[MM * NQKV], g_qkv_l[MM * NQKV];
__device__ __nv_bfloat16 g_ctx_h[MM * CD],  g_ctx_l[MM * CD];

// ---------------- helpers ----------------
__device__ __forceinline__ uint32_t smem_u32(const void* p) {
    uint32_t a;
    asm("{ .reg .u64 t; cvta.to.shared.u64 t, %1; cvt.u32.u64 %0, t; }" : "=r"(a) : "l"(p));
    return a;
}
__device__ __forceinline__ uint32_t packbf(float lo, float hi) {
    uint32_t r;
    asm("cvt.rn.bf16x2.f32 %0, %1, %2;" : "=r"(r) : "f"(hi), "f"(lo));
    return r;
}
__device__ __forceinline__ void split2(float x, float y, uint32_t& h, uint32_t& l) {
    __nv_bfloat16 hx = __float2bfloat16_rn(x), hy = __float2bfloat16_rn(y);
    h = ((uint32_t)__bfloat16_as_ushort(hy) << 16) | (uint32_t)__bfloat16_as_ushort(hx);
    l = packbf(x - __bfloat162float(hx), y - __bfloat162float(hy));
}

__device__ __forceinline__ void mma16816(float* d, const uint32_t* a, const uint32_t* b) {
    asm volatile(
        "mma.sync.aligned.m16n8k16.row.col.f32.bf16.bf16.f32 "
        "{%0,%1,%2,%3}, {%4,%5,%6,%7}, {%8,%9}, {%0,%1,%2,%3};"
        : "+f"(d[0]), "+f"(d[1]), "+f"(d[2]), "+f"(d[3])
        : "r"(a[0]), "r"(a[1]), "r"(a[2]), "r"(a[3]), "r"(b[0]), "r"(b[1]));
}
__device__ __forceinline__ void ldm_x4(uint32_t* r, uint32_t addr) {
    asm volatile("ldmatrix.sync.aligned.m8n8.x4.shared.b16 {%0,%1,%2,%3}, [%4];"
                 : "=r"(r[0]), "=r"(r[1]), "=r"(r[2]), "=r"(r[3]) : "r"(addr));
}
__device__ __forceinline__ void ldm_x4t(uint32_t* r, uint32_t addr) {
    asm volatile("ldmatrix.sync.aligned.m8n8.x4.trans.shared.b16 {%0,%1,%2,%3}, [%4];"
                 : "=r"(r[0]), "=r"(r[1]), "=r"(r[2]), "=r"(r[3]) : "r"(addr));
}
__device__ __forceinline__ void cpasync16(uint32_t dst, const void* src) {
    asm volatile("cp.async.cg.shared.global [%0], [%1], 16;" :: "r"(dst), "l"(src));
}
#define CP_COMMIT() asm volatile("cp.async.commit_group;" ::: "memory")
#define CP_WAIT1()  asm volatile("cp.async.wait_group 1;" ::: "memory")
#define CP_WAIT0()  asm volatile("cp.async.wait_group 0;" ::: "memory")

// ---------------------------------------------------------------------------
// Fold LoRA into weights, emit bf16 hi/lo split
// ---------------------------------------------------------------------------
__global__ void fold_qkv_kernel(const float* __restrict__ Wq, const float* __restrict__ Wk,
                                const float* __restrict__ Wv,
                                const float* __restrict__ Aq, const float* __restrict__ Bq,
                                const float* __restrict__ Ak, const float* __restrict__ Bk,
                                const float* __restrict__ Av, const float* __restrict__ Bv) {
    int idx = blockIdx.x * blockDim.x + threadIdx.x;
    if (idx >= NQKV * CD) return;
    int n = idx / CD;
    int c = idx - n * CD;
    const float *W, *A, *B;
    int j;
    if (n < CD)          { W = Wq; A = Aq; B = Bq; j = n; }
    else if (n < 2 * CD) { W = Wk; A = Ak; B = Bk; j = n - CD; }
    else                 { W = Wv; A = Av; B = Bv; j = n - 2 * CD; }
    float acc = W[j * CD + c];
#pragma unroll
    for (int r = 0; r < RD; r++)
        acc = fmaf(B[j * RD + r], A[r * CD + c], acc);
    __nv_bfloat16 h = __float2bfloat16_rn(acc);
    g_W_h[idx] = h;
    g_W_l[idx] = __float2bfloat16_rn(acc - __bfloat162float(h));
}

__global__ void fold_o_kernel(const float* __restrict__ Wo,
                              const float* __restrict__ Ao, const float* __restrict__ Bo) {
    int idx = blockIdx.x * blockDim.x + threadIdx.x;
    if (idx >= CD * CD) return;
    int j = idx / CD;
    int c = idx - j * CD;
    float acc = Wo[idx];
#pragma unroll
    for (int r = 0; r < RD; r++)
        acc = fmaf(Bo[j * RD + r], Ao[r * CD + c], acc);
    __nv_bfloat16 h = __float2bfloat16_rn(acc);
    g_Wo_h[idx] = h;
    g_Wo_l[idx] = __float2bfloat16_rn(acc - __bfloat162float(h));
}

__global__ void convert_x_kernel(const float* __restrict__ x) {
    int idx = blockIdx.x * blockDim.x + threadIdx.x;
    if (idx >= MM * CD) return;
    float v = x[idx];
    __nv_bfloat16 h = __float2bfloat16_rn(v);
    g_x_h[idx] = h;
    g_x_l[idx] = __float2bfloat16_rn(v - __bfloat162float(h));
}

// ---------------------------------------------------------------------------
// HMMA GEMM:  C[m][n] = sum_k A[m][k]*B[n][k]  (split-bf16 x3)
// CTA tile 128x256, BK=32, 256 thr, warp tile 64x64 (8 warps as 2m x 4n).
// 1 CTA/SM, 255-reg budget. bytes/MMA = 85 -> tensor-bound, not smem-bound.
// ---------------------------------------------------------------------------
#define GA 10240                         // A array per stage: 128 rows * 80B
#define GB 20480                         // B array per stage: 256 rows * 80B
#define GSTG (2 * GA + 2 * GB)           // 61440
#define GEMM_SMEM (2 * GSTG)             // 122880

template <int OUTMODE>
__global__ __launch_bounds__(256, 1)
void gemm_tc(const __nv_bfloat16* __restrict__ Ah, const __nv_bfloat16* __restrict__ Al,
             const __nv_bfloat16* __restrict__ Bh, const __nv_bfloat16* __restrict__ Bl,
             float* __restrict__ Cf, __nv_bfloat16* __restrict__ Ch, __nv_bfloat16* __restrict__ Cl,
             int K, int N, const float* __restrict__ bias) {
    extern __shared__ char smem[];
    const uint32_t sb = smem_u32(smem);
    const int tid = threadIdx.x, lane = tid & 31, wid = tid >> 5;
    const int wm = wid & 1, wn = wid >> 1;          // warp: rows wm*64, cols wn*64
    const int bRow = blockIdx.y * 128, bCol = blockIdx.x * 256;

    float acc[4][8][4];
#pragma unroll
    for (int i = 0; i < 4; i++)
#pragma unroll
        for (int j = 0; j < 8; j++)
#pragma unroll
            for (int e = 0; e < 4; e++) acc[i][j][e] = 0.f;

    const int NIT = K / 32;
    const int arow = tid >> 2, ach = tid & 3;       // A chunk task base

    auto issue = [&](int it, int s) {
        const uint32_t dst = sb + s * GSTG;
        const size_t ko = (size_t)it * 32 + ach * 8;
        // A hi/lo: 128 rows x 4 chunks = 512 -> 2 per thread
#pragma unroll
        for (int i = 0; i < 2; i++) {
            int r = arow + 64 * i;
            cpasync16(dst + 0 * GA + r * 80 + ach * 16, Ah + (size_t)(bRow + r) * K + ko);
            cpasync16(dst + 1 * GA + r * 80 + ach * 16, Al + (size_t)(bRow + r) * K + ko);
        }
        // B hi/lo: 256 rows x 4 chunks = 1024 -> 4 per thread
#pragma unroll
        for (int i = 0; i < 4; i++) {
            int r = arow + 64 * i;
            cpasync16(dst + 2 * GA + 0 * GB + r * 80 + ach * 16, Bh + (size_t)(bCol + r) * K + ko);
            cpasync16(dst + 2 * GA + 1 * GB + r * 80 + ach * 16, Bl + (size_t)(bCol + r) * K + ko);
        }
        CP_COMMIT();
    };

    issue(0, 0);
    const int g01 = (lane >> 3) & 1, g23 = lane >> 4, l7 = lane & 7;

    for (int i = 0; i < NIT; i++) {
        if (i + 1 < NIT) { issue(i + 1, (i + 1) & 1); CP_WAIT1(); }
        else             { CP_WAIT0(); }
        __syncthreads();
        const uint32_t aB = sb + (i & 1) * GSTG;
        const uint32_t bB = aB + 2 * GA;
#pragma unroll
        for (int k0 = 0; k0 < 32; k0 += 16) {
            uint32_t bh[8][2], bl[8][2];
#pragma unroll
            for (int p = 0; p < 4; p++) {
                uint32_t t4[4];
                uint32_t bd = bB + (uint32_t)(wn * 64 + p * 16 + l7 + g23 * 8) * 80 + (k0 + g01 * 8) * 2;
                ldm_x4(t4, bd);
                bh[2 * p][0] = t4[0]; bh[2 * p][1] = t4[1];
                bh[2 * p + 1][0] = t4[2]; bh[2 * p + 1][1] = t4[3];
                ldm_x4(t4, bd + GB);
                bl[2 * p][0] = t4[0]; bl[2 * p][1] = t4[1];
                bl[2 * p + 1][0] = t4[2]; bl[2 * p + 1][1] = t4[3];
            }
#pragma unroll
            for (int mt = 0; mt < 4; mt++) {
                uint32_t ah[4], al[4];
                uint32_t ad = aB + (uint32_t)(wm * 64 + mt * 16 + l7 + g01 * 8) * 80 + (k0 + g23 * 8) * 2;
                ldm_x4(ah, ad);
                ldm_x4(al, ad + GA);
#pragma unroll
                for (int nt = 0; nt < 8; nt++) mma16816(acc[mt][nt], ah, bh[nt]);
#pragma unroll
                for (int nt = 0; nt < 8; nt++) mma16816(acc[mt][nt], ah, bl[nt]);
#pragma unroll
                for (int nt = 0; nt < 8; nt++) mma16816(acc[mt][nt], al, bh[nt]);
            }
        }
        __syncthreads();
    }

    const int rq = lane >> 2, cq = (lane & 3) * 2;
#pragma unroll
    for (int mt = 0; mt < 4; mt++) {
#pragma unroll
        for (int nt = 0; nt < 8; nt++) {
            int r = bRow + wm * 64 + mt * 16 + rq;
            int c = bCol + wn * 64 + nt * 8 + cq;
            if (OUTMODE == 1) {
                float b0 = bias[c], b1 = bias[c + 1];
                *(float2*)(Cf + (size_t)r * N + c) =
                    make_float2(acc[mt][nt][0] + b0, acc[mt][nt][1] + b1);
                *(float2*)(Cf + (size_t)(r + 8) * N + c) =
                    make_float2(acc[mt][nt][2] + b0, acc[mt][nt][3] + b1);
            } else {
                uint32_t h0, l0, h1, l1;
                split2(acc[mt][nt][0], acc[mt][nt][1], h0, l0);
                split2(acc[mt][nt][2], acc[mt][nt][3], h1, l1);
                *(uint32_t*)(Ch + (size_t)r * N + c) = h0;
                *(uint32_t*)(Cl + (size_t)r * N + c) = l0;
                *(uint32_t*)(Ch + (size_t)(r + 8) * N + c) = h1;
                *(uint32_t*)(Cl + (size_t)(r + 8) * N + c) = l1;
            }
        }
    }
}

// ---------------------------------------------------------------------------
// Tensor-core flash attention (split-bf16 x3). 256 thr, 2 CTAs/SM. (unchanged)
// ---------------------------------------------------------------------------
#define AARR 9216
#define ASTG (4 * AARR)
#define ATTN_SMEM (2 * ASTG)            // 73728

__global__ __launch_bounds__(256, 2)
void attn_tc() {
    extern __shared__ char smem[];
    const uint32_t sb = smem_u32(smem);
    const int tid = threadIdx.x, lane = tid & 31, wid = tid >> 5;
    const int b = blockIdx.z, h = blockIdx.y, qb = blockIdx.x;
    const int rq = lane >> 2, cq = (lane & 3) * 2;
    const int l7 = lane & 7, g01 = (lane >> 3) & 1, g23 = lane >> 4;

    uint32_t qh[16], ql[16];
    {
        const size_t base = (size_t)(b * SS + qb * 128 + wid * 16 + rq) * NQKV + h * DD;
#pragma unroll
        for (int kt = 0; kt < 4; kt++) {
            int c = kt * 16 + cq;
            qh[kt * 4 + 0] = *(const uint32_t*)(g_qkv_h + base + c);
            qh[kt * 4 + 1] = *(const uint32_t*)(g_qkv_h + base + (size_t)8 * NQKV + c);
            qh[kt * 4 + 2] = *(const uint32_t*)(g_qkv_h + base + c + 8);
            qh[kt * 4 + 3] = *(const uint32_t*)(g_qkv_h + base + (size_t)8 * NQKV + c + 8);
            ql[kt * 4 + 0] = *(const uint32_t*)(g_qkv_l + base + c);
            ql[kt * 4 + 1] = *(const uint32_t*)(g_qkv_l + base + (size_t)8 * NQKV + c);
            ql[kt * 4 + 2] = *(const uint32_t*)(g_qkv_l + base + c + 8);
            ql[kt * 4 + 3] = *(const uint32_t*)(g_qkv_l + base + (size_t)8 * NQKV + c + 8);
        }
    }

    float O[8][4];
#pragma unroll
    for (int i = 0; i < 8; i++)
#pragma unroll
        for (int e = 0; e < 4; e++) O[i][e] = 0.f;
    float m0 = -1e30f, m1 = -1e30f, sl0 = 0.f, sl1 = 0.f;

    const int lrow0 = tid >> 3, lch0 = tid & 7;
    const int lrow1 = (tid + 256) >> 3;
    auto issue = [&](int it, int s) {
        const uint32_t dst = sb + s * ASTG;
        const size_t r0 = (size_t)(b * SS + it * 64 + lrow0) * NQKV;
        const size_t r1 = (size_t)(b * SS + it * 64 + lrow1) * NQKV;
        const int kc = CD + h * DD + lch0 * 8, vc = 2 * CD + h * DD + lch0 * 8;
        cpasync16(dst + 0 * AARR + lrow0 * 144 + lch0 * 16, g_qkv_h + r0 + kc);
        cpasync16(dst + 0 * AARR + lrow1 * 144 + lch0 * 16, g_qkv_h + r1 + kc);
        cpasync16(dst + 1 * AARR + lrow0 * 144 + lch0 * 16, g_qkv_l + r0 + kc);
        cpasync16(dst + 1 * AARR + lrow1 * 144 + lch0 * 16, g_qkv_l + r1 + kc);
        cpasync16(dst + 2 * AARR + lrow0 * 144 + lch0 * 16, g_qkv_h + r0 + vc);
        cpasync16(dst + 2 * AARR + lrow1 * 144 + lch0 * 16, g_qkv_h + r1 + vc);
        cpasync16(dst + 3 * AARR + lrow0 * 144 + lch0 * 16, g_qkv_l + r0 + vc);
        cpasync16(dst + 3 * AARR + lrow1 * 144 + lch0 * 16, g_qkv_l + r1 + vc);
        CP_COMMIT();
    };

    issue(0, 0);
    const int NIT = SS / 64;
    for (int i = 0; i < NIT; i++) {
        if (i + 1 < NIT) { issue(i + 1, (i + 1) & 1); CP_WAIT1(); }
        else             { CP_WAIT0(); }
        __syncthreads();
        const uint32_t kH = sb + (i & 1) * ASTG;
        const uint32_t vH = kH + 2 * AARR;

        float S[8][4];
#pragma unroll
        for (int j = 0; j < 8; j++)
#pragma unroll
            for (int e = 0; e < 4; e++) S[j][e] = 0.f;
#pragma unroll
        for (int kt = 0; kt < 4; kt++) {
#pragma unroll
            for (int p = 0; p < 4; p++) {
                uint32_t kh4[4], kl4[4];
                uint32_t kd = kH + (uint32_t)(p * 16 + l7 + g23 * 8) * 144 + (kt * 16 + g01 * 8) * 2;
                ldm_x4(kh4, kd);
                ldm_x4(kl4, kd + AARR);
                mma16816(S[2 * p],     &qh[kt * 4], &kh4[0]);
                mma16816(S[2 * p],     &qh[kt * 4], &kl4[0]);
                mma16816(S[2 * p],     &ql[kt * 4], &kh4[0]);
                mma16816(S[2 * p + 1], &qh[kt * 4], &kh4[2]);
                mma16816(S[2 * p + 1], &qh[kt * 4], &kl4[2]);
                mma16816(S[2 * p + 1], &ql[kt * 4], &kh4[2]);
            }
        }

        float nm0 = m0, nm1 = m1;
#pragma unroll
        for (int j = 0; j < 8; j++) {
            S[j][0] *= 0.125f; S[j][1] *= 0.125f; S[j][2] *= 0.125f; S[j][3] *= 0.125f;
            nm0 = fmaxf(nm0, fmaxf(S[j][0], S[j][1]));
            nm1 = fmaxf(nm1, fmaxf(S[j][2], S[j][3]));
        }
        nm0 = fmaxf(nm0, __shfl_xor_sync(0xffffffff, nm0, 1));
        nm0 = fmaxf(nm0, __shfl_xor_sync(0xffffffff, nm0, 2));
        nm1 = fmaxf(nm1, __shfl_xor_sync(0xffffffff, nm1, 1));
        nm1 = fmaxf(nm1, __shfl_xor_sync(0xffffffff, nm1, 2));
        float c0 = __expf(m0 - nm0), c1 = __expf(m1 - nm1);
        m0 = nm0; m1 = nm1;
        float s0 = 0.f, s1 = 0.f;
#pragma unroll
        for (int j = 0; j < 8; j++) {
            S[j][0] = __expf(S[j][0] - m0); S[j][1] = __expf(S[j][1] - m0);
            S[j][2] = __expf(S[j][2] - m1); S[j][3] = __expf(S[j][3] - m1);
            s0 += S[j][0] + S[j][1];
            s1 += S[j][2] + S[j][3];
        }
        s0 += __shfl_xor_sync(0xffffffff, s0, 1);
        s0 += __shfl_xor_sync(0xffffffff, s0, 2);
        s1 += __shfl_xor_sync(0xffffffff, s1, 1);
        s1 += __shfl_xor_sync(0xffffffff, s1, 2);
        sl0 = sl0 * c0 + s0;
        sl1 = sl1 * c1 + s1;
#pragma unroll
        for (int nt = 0; nt < 8; nt++) {
            O[nt][0] *= c0; O[nt][1] *= c0; O[nt][2] *= c1; O[nt][3] *= c1;
        }

#pragma unroll
        for (int kt = 0; kt < 4; kt++) {
            uint32_t ph[4], pl[4];
            split2(S[2 * kt][0],     S[2 * kt][1],     ph[0], pl[0]);
            split2(S[2 * kt][2],     S[2 * kt][3],     ph[1], pl[1]);
            split2(S[2 * kt + 1][0], S[2 * kt + 1][1], ph[2], pl[2]);
            split2(S[2 * kt + 1][2], S[2 * kt + 1][3], ph[3], pl[3]);
#pragma unroll
            for (int p = 0; p < 4; p++) {
                uint32_t vh4[4], vl4[4];
                uint32_t vd = vH + (uint32_t)(kt * 16 + l7 + g01 * 8) * 144 + (p * 16 + g23 * 8) * 2;
                ldm_x4t(vh4, vd);
                ldm_x4t(vl4, vd + AARR);
                mma16816(O[2 * p],     ph, &vh4[0]);
                mma16816(O[2 * p],     ph, &vl4[0]);
                mma16816(O[2 * p],     pl, &vh4[0]);
                mma16816(O[2 * p + 1], ph, &vh4[2]);
                mma16816(O[2 * p + 1], ph, &vl4[2]);
                mma16816(O[2 * p + 1], pl, &vh4[2]);
            }
        }
        __syncthreads();
    }

    const float i0 = 1.f / sl0, i1 = 1.f / sl1;
    const size_t rb0 = (size_t)(b * SS + qb * 128 + wid * 16 + rq) * CD + h * DD;
    const size_t rb1 = rb0 + (size_t)8 * CD;
#pragma unroll
    for (int nt = 0; nt < 8; nt++) {
        int c = nt * 8 + cq;
        uint32_t h0, l0, h1, l1;
        split2(O[nt][0] * i0, O[nt][1] * i0, h0, l0);
        split2(O[nt][2] * i1, O[nt][3] * i1, h1, l1);
        *(uint32_t*)(g_ctx_h + rb0 + c) = h0;
        *(uint32_t*)(g_ctx_l + rb0 + c) = l0;
        *(uint32_t*)(g_ctx_h + rb1 + c) = h1;
        *(uint32_t*)(g_ctx_l + rb1 + c) = l1;
    }
}

// ---------------------------------------------------------------------------
// Launch
// ---------------------------------------------------------------------------
extern "C" void kernel_launch(void* const* d_in, const int* in_sizes, int n_in,
                              void* d_out, int out_size) {
    const float* x  = (const float*)d_in[0];
    const float* Wq = (const float*)d_in[1];
    const float* Wk = (const float*)d_in[2];
    const float* Wv = (const float*)d_in[3];
    const float* Wo = (const float*)d_in[4];
    const float* bo = (const float*)d_in[5];
    const float* Aq = (const float*)d_in[6];
    const float* Bq = (const float*)d_in[7];
    const float* Ak = (const float*)d_in[8];
    const float* Bk = (const float*)d_in[9];
    const float* Av = (const float*)d_in[10];
    const float* Bv = (const float*)d_in[11];
    const float* Ao = (const float*)d_in[12];
    const float* Bo = (const float*)d_in[13];

    static __nv_bfloat16 *p_xh, *p_xl, *p_Wh, *p_Wl, *p_Woh, *p_Wol, *p_qh, *p_ql, *p_ch, *p_cl;
    static bool init = false;
    if (!init) {
        cudaGetSymbolAddress((void**)&p_xh, g_x_h);
        cudaGetSymbolAddress((void**)&p_xl, g_x_l);
        cudaGetSymbolAddress((void**)&p_Wh, g_W_h);
        cudaGetSymbolAddress((void**)&p_Wl, g_W_l);
        cudaGetSymbolAddress((void**)&p_Woh, g_Wo_h);
        cudaGetSymbolAddress((void**)&p_Wol, g_Wo_l);
        cudaGetSymbolAddress((void**)&p_qh, g_qkv_h);
        cudaGetSymbolAddress((void**)&p_ql, g_qkv_l);
        cudaGetSymbolAddress((void**)&p_ch, g_ctx_h);
        cudaGetSymbolAddress((void**)&p_cl, g_ctx_l);
        cudaFuncSetAttribute(gemm_tc<0>, cudaFuncAttributeMaxDynamicSharedMemorySize, GEMM_SMEM);
        cudaFuncSetAttribute(gemm_tc<1>, cudaFuncAttributeMaxDynamicSharedMemorySize, GEMM_SMEM);
        cudaFuncSetAttribute(attn_tc, cudaFuncAttributeMaxDynamicSharedMemorySize, ATTN_SMEM);
        init = true;
    }

    fold_qkv_kernel<<<(NQKV * CD + 255) / 256, 256>>>(Wq, Wk, Wv, Aq, Bq, Ak, Bk, Av, Bv);
    fold_o_kernel<<<(CD * CD + 255) / 256, 256>>>(Wo, Ao, Bo);
    convert_x_kernel<<<(MM * CD + 255) / 256, 256>>>(x);

    // QKV projection: tiles 128m x 256n
    gemm_tc<0><<<dim3(NQKV / 256, MM / 128), 256, GEMM_SMEM>>>(
        p_xh, p_xl, p_Wh, p_Wl, nullptr, p_qh, p_ql, CD, NQKV, nullptr);

    attn_tc<<<dim3(SS / 128, HH, BB), 256, ATTN_SMEM>>>();

    gemm_tc<1><<<dim3(CD / 256, MM / 128), 256, GEMM_SMEM>>>(
        p_ch, p_cl, p_Woh, p_Wol, (float*)d_out, nullptr, nullptr, CD, CD, bo);
}

// round 7
// speedup vs baseline: 1.1306x; 1.1306x over previous
#include <cuda_runtime.h>
#include <cuda_bf16.h>
#include <cstdint>

#define CD 1280
#define RD 4
#define BB 2
#define SS 2048
#define MM 4096
#define HH 20
#define DD 64
#define NQKV 3840

// ---------------- device scratch (bf16 hi/lo split operands) ----------------
__device__ __nv_bfloat16 g_x_h[MM * CD],    g_x_l[MM * CD];
__device__ __nv_bfloat16 g_W_h[NQKV * CD],  g_W_l[NQKV * CD];
__device__ __nv_bfloat16 g_Wo_h[CD * CD],   g_Wo_l[CD * CD];
__device__ __nv_bfloat16 g_qkv_h[MM * NQKV], g_qkv_l[MM * NQKV];
__device__ __nv_bfloat16 g_ctx_h[MM * CD],  g_ctx_l[MM * CD];

// ---------------- helpers ----------------
__device__ __forceinline__ uint32_t smem_u32(const void* p) {
    uint32_t a;
    asm("{ .reg .u64 t; cvta.to.shared.u64 t, %1; cvt.u32.u64 %0, t; }" : "=r"(a) : "l"(p));
    return a;
}
__device__ __forceinline__ uint32_t packbf(float lo, float hi) {
    uint32_t r;
    asm("cvt.rn.bf16x2.f32 %0, %1, %2;" : "=r"(r) : "f"(hi), "f"(lo));
    return r;
}
__device__ __forceinline__ void split2(float x, float y, uint32_t& h, uint32_t& l) {
    __nv_bfloat16 hx = __float2bfloat16_rn(x), hy = __float2bfloat16_rn(y);
    h = ((uint32_t)__bfloat16_as_ushort(hy) << 16) | (uint32_t)__bfloat16_as_ushort(hx);
    l = packbf(x - __bfloat162float(hx), y - __bfloat162float(hy));
}

__device__ __forceinline__ void mma16816(float* d, const uint32_t* a, const uint32_t* b) {
    asm volatile(
        "mma.sync.aligned.m16n8k16.row.col.f32.bf16.bf16.f32 "
        "{%0,%1,%2,%3}, {%4,%5,%6,%7}, {%8,%9}, {%0,%1,%2,%3};"
        : "+f"(d[0]), "+f"(d[1]), "+f"(d[2]), "+f"(d[3])
        : "r"(a[0]), "r"(a[1]), "r"(a[2]), "r"(a[3]), "r"(b[0]), "r"(b[1]));
}
__device__ __forceinline__ void ldm_x4(uint32_t* r, uint32_t addr) {
    asm volatile("ldmatrix.sync.aligned.m8n8.x4.shared.b16 {%0,%1,%2,%3}, [%4];"
                 : "=r"(r[0]), "=r"(r[1]), "=r"(r[2]), "=r"(r[3]) : "r"(addr));
}
__device__ __forceinline__ void ldm_x4t(uint32_t* r, uint32_t addr) {
    asm volatile("ldmatrix.sync.aligned.m8n8.x4.trans.shared.b16 {%0,%1,%2,%3}, [%4];"
                 : "=r"(r[0]), "=r"(r[1]), "=r"(r[2]), "=r"(r[3]) : "r"(addr));
}
__device__ __forceinline__ void cpasync16(uint32_t dst, const void* src) {
    asm volatile("cp.async.cg.shared.global [%0], [%1], 16;" :: "r"(dst), "l"(src));
}
#define CP_COMMIT() asm volatile("cp.async.commit_group;" ::: "memory")
#define CP_WAIT1()  asm volatile("cp.async.wait_group 1;" ::: "memory")
#define CP_WAIT0()  asm volatile("cp.async.wait_group 0;" ::: "memory")

// ---------------------------------------------------------------------------
// Fold LoRA into weights, emit bf16 hi/lo split
// ---------------------------------------------------------------------------
__global__ void fold_qkv_kernel(const float* __restrict__ Wq, const float* __restrict__ Wk,
                                const float* __restrict__ Wv,
                                const float* __restrict__ Aq, const float* __restrict__ Bq,
                                const float* __restrict__ Ak, const float* __restrict__ Bk,
                                const float* __restrict__ Av, const float* __restrict__ Bv) {
    int idx = blockIdx.x * blockDim.x + threadIdx.x;
    if (idx >= NQKV * CD) return;
    int n = idx / CD;
    int c = idx - n * CD;
    const float *W, *A, *B;
    int j;
    if (n < CD)          { W = Wq; A = Aq; B = Bq; j = n; }
    else if (n < 2 * CD) { W = Wk; A = Ak; B = Bk; j = n - CD; }
    else                 { W = Wv; A = Av; B = Bv; j = n - 2 * CD; }
    float acc = W[j * CD + c];
#pragma unroll
    for (int r = 0; r < RD; r++)
        acc = fmaf(B[j * RD + r], A[r * CD + c], acc);
    __nv_bfloat16 h = __float2bfloat16_rn(acc);
    g_W_h[idx] = h;
    g_W_l[idx] = __float2bfloat16_rn(acc - __bfloat162float(h));
}

__global__ void fold_o_kernel(const float* __restrict__ Wo,
                              const float* __restrict__ Ao, const float* __restrict__ Bo) {
    int idx = blockIdx.x * blockDim.x + threadIdx.x;
    if (idx >= CD * CD) return;
    int j = idx / CD;
    int c = idx - j * CD;
    float acc = Wo[idx];
#pragma unroll
    for (int r = 0; r < RD; r++)
        acc = fmaf(Bo[j * RD + r], Ao[r * CD + c], acc);
    __nv_bfloat16 h = __float2bfloat16_rn(acc);
    g_Wo_h[idx] = h;
    g_Wo_l[idx] = __float2bfloat16_rn(acc - __bfloat162float(h));
}

__global__ void convert_x_kernel(const float* __restrict__ x) {
    int idx = blockIdx.x * blockDim.x + threadIdx.x;
    if (idx >= MM * CD) return;
    float v = x[idx];
    __nv_bfloat16 h = __float2bfloat16_rn(v);
    g_x_h[idx] = h;
    g_x_l[idx] = __float2bfloat16_rn(v - __bfloat162float(h));
}

// ---------------------------------------------------------------------------
// HMMA GEMM:  C[m][n] = sum_k A[m][k]*B[n][k]  (split-bf16 x3)
// BM=128, BN=128, BK=32, 256 thr, 2 CTAs/SM (128-reg budget).
// Pass-separated MMA ordering: acc RAW distance 4.
// ---------------------------------------------------------------------------
#define GARR 10240
#define GSTG (4 * GARR)
#define GEMM_SMEM (2 * GSTG)            // 81920

template <int OUTMODE>
__global__ __launch_bounds__(256, 2)
void gemm_tc(const __nv_bfloat16* __restrict__ Ah, const __nv_bfloat16* __restrict__ Al,
             const __nv_bfloat16* __restrict__ Bh, const __nv_bfloat16* __restrict__ Bl,
             float* __restrict__ Cf, __nv_bfloat16* __restrict__ Ch, __nv_bfloat16* __restrict__ Cl,
             int K, int N, const float* __restrict__ bias) {
    extern __shared__ char smem[];
    const uint32_t sb = smem_u32(smem);
    const int tid = threadIdx.x, lane = tid & 31, wid = tid >> 5;
    const int wm = wid & 1, wn = wid >> 1;
    const int bRow = blockIdx.y * 128, bCol = blockIdx.x * 128;

    float acc[4][4][4];
#pragma unroll
    for (int i = 0; i < 4; i++)
#pragma unroll
        for (int j = 0; j < 4; j++)
#pragma unroll
            for (int e = 0; e < 4; e++) acc[i][j][e] = 0.f;

    const int NIT = K / 32;
    const int row0 = tid >> 2, ch0 = tid & 3;
    const int row1 = (tid + 256) >> 2;

    auto issue = [&](int it, int s) {
        const uint32_t dst = sb + s * GSTG;
        const size_t ko = (size_t)it * 32 + ch0 * 8;
        cpasync16(dst + 0 * GARR + row0 * 80 + ch0 * 16, Ah + (size_t)(bRow + row0) * K + ko);
        cpasync16(dst + 0 * GARR + row1 * 80 + ch0 * 16, Ah + (size_t)(bRow + row1) * K + ko);
        cpasync16(dst + 1 * GARR + row0 * 80 + ch0 * 16, Al + (size_t)(bRow + row0) * K + ko);
        cpasync16(dst + 1 * GARR + row1 * 80 + ch0 * 16, Al + (size_t)(bRow + row1) * K + ko);
        cpasync16(dst + 2 * GARR + row0 * 80 + ch0 * 16, Bh + (size_t)(bCol + row0) * K + ko);
        cpasync16(dst + 2 * GARR + row1 * 80 + ch0 * 16, Bh + (size_t)(bCol + row1) * K + ko);
        cpasync16(dst + 3 * GARR + row0 * 80 + ch0 * 16, Bl + (size_t)(bCol + row0) * K + ko);
        cpasync16(dst + 3 * GARR + row1 * 80 + ch0 * 16, Bl + (size_t)(bCol + row1) * K + ko);
        CP_COMMIT();
    };

    issue(0, 0);
    const int g01 = (lane >> 3) & 1, g23 = lane >> 4, l7 = lane & 7;

    for (int i = 0; i < NIT; i++) {
        if (i + 1 < NIT) { issue(i + 1, (i + 1) & 1); CP_WAIT1(); }
        else             { CP_WAIT0(); }
        __syncthreads();
        const uint32_t aH = sb + (i & 1) * GSTG;
        const uint32_t bH = aH + 2 * GARR;
#pragma unroll
        for (int k0 = 0; k0 < 32; k0 += 16) {
            uint32_t bh[4][2], bl[4][2];
#pragma unroll
            for (int p = 0; p < 2; p++) {
                uint32_t bt[4], bt2[4];
                uint32_t bd = bH + (uint32_t)(wn * 32 + p * 16 + l7 + g23 * 8) * 80 + (k0 + g01 * 8) * 2;
                ldm_x4(bt, bd);
                ldm_x4(bt2, bd + GARR);
                bh[2 * p][0] = bt[0]; bh[2 * p][1] = bt[1];
                bh[2 * p + 1][0] = bt[2]; bh[2 * p + 1][1] = bt[3];
                bl[2 * p][0] = bt2[0]; bl[2 * p][1] = bt2[1];
                bl[2 * p + 1][0] = bt2[2]; bl[2 * p + 1][1] = bt2[3];
            }
#pragma unroll
            for (int mt = 0; mt < 4; mt++) {
                uint32_t ah[4], al[4];
                uint32_t ad = aH + (uint32_t)(wm * 64 + mt * 16 + l7 + g01 * 8) * 80 + (k0 + g23 * 8) * 2;
                ldm_x4(ah, ad);
                ldm_x4(al, ad + GARR);
                // pass-separated: RAW distance 4 on each acc
#pragma unroll
                for (int nt = 0; nt < 4; nt++) mma16816(acc[mt][nt], ah, bh[nt]);
#pragma unroll
                for (int nt = 0; nt < 4; nt++) mma16816(acc[mt][nt], ah, bl[nt]);
#pragma unroll
                for (int nt = 0; nt < 4; nt++) mma16816(acc[mt][nt], al, bh[nt]);
            }
        }
        __syncthreads();
    }

    const int rq = lane >> 2, cq = (lane & 3) * 2;
#pragma unroll
    for (int mt = 0; mt < 4; mt++) {
#pragma unroll
        for (int nt = 0; nt < 4; nt++) {
            int r = bRow + wm * 64 + mt * 16 + rq;
            int c = bCol + wn * 32 + nt * 8 + cq;
            if (OUTMODE == 1) {
                float b0 = bias[c], b1 = bias[c + 1];
                *(float2*)(Cf + (size_t)r * N + c) =
                    make_float2(acc[mt][nt][0] + b0, acc[mt][nt][1] + b1);
                *(float2*)(Cf + (size_t)(r + 8) * N + c) =
                    make_float2(acc[mt][nt][2] + b0, acc[mt][nt][3] + b1);
            } else {
                uint32_t h0, l0, h1, l1;
                split2(acc[mt][nt][0], acc[mt][nt][1], h0, l0);
                split2(acc[mt][nt][2], acc[mt][nt][3], h1, l1);
                *(uint32_t*)(Ch + (size_t)r * N + c) = h0;
                *(uint32_t*)(Cl + (size_t)r * N + c) = l0;
                *(uint32_t*)(Ch + (size_t)(r + 8) * N + c) = h1;
                *(uint32_t*)(Cl + (size_t)(r + 8) * N + c) = l1;
            }
        }
    }
}

// ---------------------------------------------------------------------------
// Tensor-core flash attention (split-bf16 x3). 256 thr, 2 CTAs/SM.
// MMA ordering interleaved across acc pairs: RAW distance 2.
// ---------------------------------------------------------------------------
#define AARR 9216
#define ASTG (4 * AARR)
#define ATTN_SMEM (2 * ASTG)            // 73728

__global__ __launch_bounds__(256, 2)
void attn_tc() {
    extern __shared__ char smem[];
    const uint32_t sb = smem_u32(smem);
    const int tid = threadIdx.x, lane = tid & 31, wid = tid >> 5;
    const int b = blockIdx.z, h = blockIdx.y, qb = blockIdx.x;
    const int rq = lane >> 2, cq = (lane & 3) * 2;
    const int l7 = lane & 7, g01 = (lane >> 3) & 1, g23 = lane >> 4;

    uint32_t qh[16], ql[16];
    {
        const size_t base = (size_t)(b * SS + qb * 128 + wid * 16 + rq) * NQKV + h * DD;
#pragma unroll
        for (int kt = 0; kt < 4; kt++) {
            int c = kt * 16 + cq;
            qh[kt * 4 + 0] = *(const uint32_t*)(g_qkv_h + base + c);
            qh[kt * 4 + 1] = *(const uint32_t*)(g_qkv_h + base + (size_t)8 * NQKV + c);
            qh[kt * 4 + 2] = *(const uint32_t*)(g_qkv_h + base + c + 8);
            qh[kt * 4 + 3] = *(const uint32_t*)(g_qkv_h + base + (size_t)8 * NQKV + c + 8);
            ql[kt * 4 + 0] = *(const uint32_t*)(g_qkv_l + base + c);
            ql[kt * 4 + 1] = *(const uint32_t*)(g_qkv_l + base + (size_t)8 * NQKV + c);
            ql[kt * 4 + 2] = *(const uint32_t*)(g_qkv_l + base + c + 8);
            ql[kt * 4 + 3] = *(const uint32_t*)(g_qkv_l + base + (size_t)8 * NQKV + c + 8);
        }
    }

    float O[8][4];
#pragma unroll
    for (int i = 0; i < 8; i++)
#pragma unroll
        for (int e = 0; e < 4; e++) O[i][e] = 0.f;
    float m0 = -1e30f, m1 = -1e30f, sl0 = 0.f, sl1 = 0.f;

    const int lrow0 = tid >> 3, lch0 = tid & 7;
    const int lrow1 = (tid + 256) >> 3;
    auto issue = [&](int it, int s) {
        const uint32_t dst = sb + s * ASTG;
        const size_t r0 = (size_t)(b * SS + it * 64 + lrow0) * NQKV;
        const size_t r1 = (size_t)(b * SS + it * 64 + lrow1) * NQKV;
        const int kc = CD + h * DD + lch0 * 8, vc = 2 * CD + h * DD + lch0 * 8;
        cpasync16(dst + 0 * AARR + lrow0 * 144 + lch0 * 16, g_qkv_h + r0 + kc);
        cpasync16(dst + 0 * AARR + lrow1 * 144 + lch0 * 16, g_qkv_h + r1 + kc);
        cpasync16(dst + 1 * AARR + lrow0 * 144 + lch0 * 16, g_qkv_l + r0 + kc);
        cpasync16(dst + 1 * AARR + lrow1 * 144 + lch0 * 16, g_qkv_l + r1 + kc);
        cpasync16(dst + 2 * AARR + lrow0 * 144 + lch0 * 16, g_qkv_h + r0 + vc);
        cpasync16(dst + 2 * AARR + lrow1 * 144 + lch0 * 16, g_qkv_h + r1 + vc);
        cpasync16(dst + 3 * AARR + lrow0 * 144 + lch0 * 16, g_qkv_l + r0 + vc);
        cpasync16(dst + 3 * AARR + lrow1 * 144 + lch0 * 16, g_qkv_l + r1 + vc);
        CP_COMMIT();
    };

    issue(0, 0);
    const int NIT = SS / 64;
    for (int i = 0; i < NIT; i++) {
        if (i + 1 < NIT) { issue(i + 1, (i + 1) & 1); CP_WAIT1(); }
        else             { CP_WAIT0(); }
        __syncthreads();
        const uint32_t kH = sb + (i & 1) * ASTG;
        const uint32_t vH = kH + 2 * AARR;

        float S[8][4];
#pragma unroll
        for (int j = 0; j < 8; j++)
#pragma unroll
            for (int e = 0; e < 4; e++) S[j][e] = 0.f;
#pragma unroll
        for (int kt = 0; kt < 4; kt++) {
#pragma unroll
            for (int p = 0; p < 4; p++) {
                uint32_t kh4[4], kl4[4];
                uint32_t kd = kH + (uint32_t)(p * 16 + l7 + g23 * 8) * 144 + (kt * 16 + g01 * 8) * 2;
                ldm_x4(kh4, kd);
                ldm_x4(kl4, kd + AARR);
                // interleaved passes: RAW distance 2
                mma16816(S[2 * p],     &qh[kt * 4], &kh4[0]);
                mma16816(S[2 * p + 1], &qh[kt * 4], &kh4[2]);
                mma16816(S[2 * p],     &qh[kt * 4], &kl4[0]);
                mma16816(S[2 * p + 1], &qh[kt * 4], &kl4[2]);
                mma16816(S[2 * p],     &ql[kt * 4], &kh4[0]);
                mma16816(S[2 * p + 1], &ql[kt * 4], &kh4[2]);
            }
        }

        float nm0 = m0, nm1 = m1;
#pragma unroll
        for (int j = 0; j < 8; j++) {
            S[j][0] *= 0.125f; S[j][1] *= 0.125f; S[j][2] *= 0.125f; S[j][3] *= 0.125f;
            nm0 = fmaxf(nm0, fmaxf(S[j][0], S[j][1]));
            nm1 = fmaxf(nm1, fmaxf(S[j][2], S[j][3]));
        }
        nm0 = fmaxf(nm0, __shfl_xor_sync(0xffffffff, nm0, 1));
        nm0 = fmaxf(nm0, __shfl_xor_sync(0xffffffff, nm0, 2));
        nm1 = fmaxf(nm1, __shfl_xor_sync(0xffffffff, nm1, 1));
        nm1 = fmaxf(nm1, __shfl_xor_sync(0xffffffff, nm1, 2));
        float c0 = __expf(m0 - nm0), c1 = __expf(m1 - nm1);
        m0 = nm0; m1 = nm1;
        float s0 = 0.f, s1 = 0.f;
#pragma unroll
        for (int j = 0; j < 8; j++) {
            S[j][0] = __expf(S[j][0] - m0); S[j][1] = __expf(S[j][1] - m0);
            S[j][2] = __expf(S[j][2] - m1); S[j][3] = __expf(S[j][3] - m1);
            s0 += S[j][0] + S[j][1];
            s1 += S[j][2] + S[j][3];
        }
        s0 += __shfl_xor_sync(0xffffffff, s0, 1);
        s0 += __shfl_xor_sync(0xffffffff, s0, 2);
        s1 += __shfl_xor_sync(0xffffffff, s1, 1);
        s1 += __shfl_xor_sync(0xffffffff, s1, 2);
        sl0 = sl0 * c0 + s0;
        sl1 = sl1 * c1 + s1;
#pragma unroll
        for (int nt = 0; nt < 8; nt++) {
            O[nt][0] *= c0; O[nt][1] *= c0; O[nt][2] *= c1; O[nt][3] *= c1;
        }

#pragma unroll
        for (int kt = 0; kt < 4; kt++) {
            uint32_t ph[4], pl[4];
            split2(S[2 * kt][0],     S[2 * kt][1],     ph[0], pl[0]);
            split2(S[2 * kt][2],     S[2 * kt][3],     ph[1], pl[1]);
            split2(S[2 * kt + 1][0], S[2 * kt + 1][1], ph[2], pl[2]);
            split2(S[2 * kt + 1][2], S[2 * kt + 1][3], ph[3], pl[3]);
#pragma unroll
            for (int p = 0; p < 4; p++) {
                uint32_t vh4[4], vl4[4];
                uint32_t vd = vH + (uint32_t)(kt * 16 + l7 + g01 * 8) * 144 + (p * 16 + g23 * 8) * 2;
                ldm_x4t(vh4, vd);
                ldm_x4t(vl4, vd + AARR);
                // interleaved passes: RAW distance 2
                mma16816(O[2 * p],     ph, &vh4[0]);
                mma16816(O[2 * p + 1], ph, &vh4[2]);
                mma16816(O[2 * p],     ph, &vl4[0]);
                mma16816(O[2 * p + 1], ph, &vl4[2]);
                mma16816(O[2 * p],     pl, &vh4[0]);
                mma16816(O[2 * p + 1], pl, &vh4[2]);
            }
        }
        __syncthreads();
    }

    const float i0 = 1.f / sl0, i1 = 1.f / sl1;
    const size_t rb0 = (size_t)(b * SS + qb * 128 + wid * 16 + rq) * CD + h * DD;
    const size_t rb1 = rb0 + (size_t)8 * CD;
#pragma unroll
    for (int nt = 0; nt < 8; nt++) {
        int c = nt * 8 + cq;
        uint32_t h0, l0, h1, l1;
        split2(O[nt][0] * i0, O[nt][1] * i0, h0, l0);
        split2(O[nt][2] * i1, O[nt][3] * i1, h1, l1);
        *(uint32_t*)(g_ctx_h + rb0 + c) = h0;
        *(uint32_t*)(g_ctx_l + rb0 + c) = l0;
        *(uint32_t*)(g_ctx_h + rb1 + c) = h1;
        *(uint32_t*)(g_ctx_l + rb1 + c) = l1;
    }
}

// ---------------------------------------------------------------------------
// Launch
// ---------------------------------------------------------------------------
extern "C" void kernel_launch(void* const* d_in, const int* in_sizes, int n_in,
                              void* d_out, int out_size) {
    const float* x  = (const float*)d_in[0];
    const float* Wq = (const float*)d_in[1];
    const float* Wk = (const float*)d_in[2];
    const float* Wv = (const float*)d_in[3];
    const float* Wo = (const float*)d_in[4];
    const float* bo = (const float*)d_in[5];
    const float* Aq = (const float*)d_in[6];
    const float* Bq = (const float*)d_in[7];
    const float* Ak = (const float*)d_in[8];
    const float* Bk = (const float*)d_in[9];
    const float* Av = (const float*)d_in[10];
    const float* Bv = (const float*)d_in[11];
    const float* Ao = (const float*)d_in[12];
    const float* Bo = (const float*)d_in[13];

    static __nv_bfloat16 *p_xh, *p_xl, *p_Wh, *p_Wl, *p_Woh, *p_Wol, *p_qh, *p_ql, *p_ch, *p_cl;
    static bool init = false;
    if (!init) {
        cudaGetSymbolAddress((void**)&p_xh, g_x_h);
        cudaGetSymbolAddress((void**)&p_xl, g_x_l);
        cudaGetSymbolAddress((void**)&p_Wh, g_W_h);
        cudaGetSymbolAddress((void**)&p_Wl, g_W_l);
        cudaGetSymbolAddress((void**)&p_Woh, g_Wo_h);
        cudaGetSymbolAddress((void**)&p_Wol, g_Wo_l);
        cudaGetSymbolAddress((void**)&p_qh, g_qkv_h);
        cudaGetSymbolAddress((void**)&p_ql, g_qkv_l);
        cudaGetSymbolAddress((void**)&p_ch, g_ctx_h);
        cudaGetSymbolAddress((void**)&p_cl, g_ctx_l);
        cudaFuncSetAttribute(gemm_tc<0>, cudaFuncAttributeMaxDynamicSharedMemorySize, GEMM_SMEM);
        cudaFuncSetAttribute(gemm_tc<1>, cudaFuncAttributeMaxDynamicSharedMemorySize, GEMM_SMEM);
        cudaFuncSetAttribute(attn_tc, cudaFuncAttributeMaxDynamicSharedMemorySize, ATTN_SMEM);
        init = true;
    }

    fold_qkv_kernel<<<(NQKV * CD + 255) / 256, 256>>>(Wq, Wk, Wv, Aq, Bq, Ak, Bk, Av, Bv);
    fold_o_kernel<<<(CD * CD + 255) / 256, 256>>>(Wo, Ao, Bo);
    convert_x_kernel<<<(MM * CD + 255) / 256, 256>>>(x);

    gemm_tc<0><<<dim3(NQKV / 128, MM / 128), 256, GEMM_SMEM>>>(
        p_xh, p_xl, p_Wh, p_Wl, nullptr, p_qh, p_ql, CD, NQKV, nullptr);

    attn_tc<<<dim3(SS / 128, HH, BB), 256, ATTN_SMEM>>>();

    gemm_tc<1><<<dim3(CD / 128, MM / 128), 256, GEMM_SMEM>>>(
        p_ch, p_cl, p_Woh, p_Wol, (float*)d_out, nullptr, nullptr, CD, CD, bo);
}

// round 8
// speedup vs baseline: 1.5797x; 1.3972x over previous
#include <cuda_runtime.h>
#include <cuda_fp16.h>
#include <cstdint>

#define CD 1280
#define RD 4
#define BB 2
#define SS 2048
#define MM 4096
#define HH 20
#define DD 64
#define NQKV 3840

// ---------------- device scratch (fp16; weights/K/V split hi+lo) ----------------
__device__ __half g_x_h[MM * CD];
__device__ __half g_W_h[NQKV * CD],  g_W_l[NQKV * CD];
__device__ __half g_Wo_h[CD * CD],   g_Wo_l[CD * CD];
__device__ __half g_qkv_h[MM * NQKV], g_qkv_l[MM * NQKV];
__device__ __half g_ctx_h[MM * CD];

// ---------------- helpers ----------------
__device__ __forceinline__ uint32_t smem_u32(const void* p) {
    uint32_t a;
    asm("{ .reg .u64 t; cvta.to.shared.u64 t, %1; cvt.u32.u64 %0, t; }" : "=r"(a) : "l"(p));
    return a;
}
// pack {lo, hi} floats -> f16x2 (lo in bits [15:0])
__device__ __forceinline__ uint32_t packh(float lo, float hi) {
    uint32_t r;
    asm("cvt.rn.f16x2.f32 %0, %1, %2;" : "=r"(r) : "f"(hi), "f"(lo));
    return r;
}
// split pair (x,y) into hi f16x2 and residual-lo f16x2
__device__ __forceinline__ void split2(float x, float y, uint32_t& h, uint32_t& l) {
    __half hx = __float2half_rn(x), hy = __float2half_rn(y);
    h = ((uint32_t)__half_as_ushort(hy) << 16) | (uint32_t)__half_as_ushort(hx);
    l = packh(x - __half2float(hx), y - __half2float(hy));
}

__device__ __forceinline__ void mma16816(float* d, const uint32_t* a, const uint32_t* b) {
    asm volatile(
        "mma.sync.aligned.m16n8k16.row.col.f32.f16.f16.f32 "
        "{%0,%1,%2,%3}, {%4,%5,%6,%7}, {%8,%9}, {%0,%1,%2,%3};"
        : "+f"(d[0]), "+f"(d[1]), "+f"(d[2]), "+f"(d[3])
        : "r"(a[0]), "r"(a[1]), "r"(a[2]), "r"(a[3]), "r"(b[0]), "r"(b[1]));
}
__device__ __forceinline__ void ldm_x4(uint32_t* r, uint32_t addr) {
    asm volatile("ldmatrix.sync.aligned.m8n8.x4.shared.b16 {%0,%1,%2,%3}, [%4];"
                 : "=r"(r[0]), "=r"(r[1]), "=r"(r[2]), "=r"(r[3]) : "r"(addr));
}
__device__ __forceinline__ void ldm_x4t(uint32_t* r, uint32_t addr) {
    asm volatile("ldmatrix.sync.aligned.m8n8.x4.trans.shared.b16 {%0,%1,%2,%3}, [%4];"
                 : "=r"(r[0]), "=r"(r[1]), "=r"(r[2]), "=r"(r[3]) : "r"(addr));
}
__device__ __forceinline__ void cpasync16(uint32_t dst, const void* src) {
    asm volatile("cp.async.cg.shared.global [%0], [%1], 16;" :: "r"(dst), "l"(src));
}
#define CP_COMMIT() asm volatile("cp.async.commit_group;" ::: "memory")
#define CP_WAIT1()  asm volatile("cp.async.wait_group 1;" ::: "memory")
#define CP_WAIT0()  asm volatile("cp.async.wait_group 0;" ::: "memory")

// ---------------------------------------------------------------------------
// Fold LoRA into weights, emit fp16 hi/lo split
// ---------------------------------------------------------------------------
__global__ void fold_qkv_kernel(const float* __restrict__ Wq, const float* __restrict__ Wk,
                                const float* __restrict__ Wv,
                                const float* __restrict__ Aq, const float* __restrict__ Bq,
                                const float* __restrict__ Ak, const float* __restrict__ Bk,
                                const float* __restrict__ Av, const float* __restrict__ Bv) {
    int idx = blockIdx.x * blockDim.x + threadIdx.x;
    if (idx >= NQKV * CD) return;
    int n = idx / CD;
    int c = idx - n * CD;
    const float *W, *A, *B;
    int j;
    if (n < CD)          { W = Wq; A = Aq; B = Bq; j = n; }
    else if (n < 2 * CD) { W = Wk; A = Ak; B = Bk; j = n - CD; }
    else                 { W = Wv; A = Av; B = Bv; j = n - 2 * CD; }
    float acc = W[j * CD + c];
#pragma unroll
    for (int r = 0; r < RD; r++)
        acc = fmaf(B[j * RD + r], A[r * CD + c], acc);
    __half h = __float2half_rn(acc);
    g_W_h[idx] = h;
    g_W_l[idx] = __float2half_rn(acc - __half2float(h));
}

__global__ void fold_o_kernel(const float* __restrict__ Wo,
                              const float* __restrict__ Ao, const float* __restrict__ Bo) {
    int idx = blockIdx.x * blockDim.x + threadIdx.x;
    if (idx >= CD * CD) return;
    int j = idx / CD;
    int c = idx - j * CD;
    float acc = Wo[idx];
#pragma unroll
    for (int r = 0; r < RD; r++)
        acc = fmaf(Bo[j * RD + r], Ao[r * CD + c], acc);
    __half h = __float2half_rn(acc);
    g_Wo_h[idx] = h;
    g_Wo_l[idx] = __float2half_rn(acc - __half2float(h));
}

__global__ void convert_x_kernel(const float* __restrict__ x) {
    int idx = blockIdx.x * blockDim.x + threadIdx.x;
    if (idx >= MM * CD) return;
    g_x_h[idx] = __float2half_rn(x[idx]);
}

// ---------------------------------------------------------------------------
// HMMA GEMM (2-pass fp16):  C[m][n] = sum_k A[m][k]*(Bh+Bl)[n][k]
// A single fp16; B split hi/lo. BM=128, BN=128, BK=32, 256 thr, 2 CTAs/SM.
// ---------------------------------------------------------------------------
#define GARR 10240
#define GSTG (3 * GARR)                 // A, Bh, Bl
#define GEMM_SMEM (2 * GSTG)            // 61440

template <int OUTMODE>
__global__ __launch_bounds__(256, 2)
void gemm_tc(const __half* __restrict__ Ah,
             const __half* __restrict__ Bh, const __half* __restrict__ Bl,
             float* __restrict__ Cf, __half* __restrict__ Ch, __half* __restrict__ Cl,
             int K, int N, const float* __restrict__ bias) {
    extern __shared__ char smem[];
    const uint32_t sb = smem_u32(smem);
    const int tid = threadIdx.x, lane = tid & 31, wid = tid >> 5;
    const int wm = wid & 1, wn = wid >> 1;
    const int bRow = blockIdx.y * 128, bCol = blockIdx.x * 128;

    float acc[4][4][4];
#pragma unroll
    for (int i = 0; i < 4; i++)
#pragma unroll
        for (int j = 0; j < 4; j++)
#pragma unroll
            for (int e = 0; e < 4; e++) acc[i][j][e] = 0.f;

    const int NIT = K / 32;
    const int row0 = tid >> 2, ch0 = tid & 3;
    const int row1 = (tid + 256) >> 2;

    auto issue = [&](int it, int s) {
        const uint32_t dst = sb + s * GSTG;
        const size_t ko = (size_t)it * 32 + ch0 * 8;
        cpasync16(dst + 0 * GARR + row0 * 80 + ch0 * 16, Ah + (size_t)(bRow + row0) * K + ko);
        cpasync16(dst + 0 * GARR + row1 * 80 + ch0 * 16, Ah + (size_t)(bRow + row1) * K + ko);
        cpasync16(dst + 1 * GARR + row0 * 80 + ch0 * 16, Bh + (size_t)(bCol + row0) * K + ko);
        cpasync16(dst + 1 * GARR + row1 * 80 + ch0 * 16, Bh + (size_t)(bCol + row1) * K + ko);
        cpasync16(dst + 2 * GARR + row0 * 80 + ch0 * 16, Bl + (size_t)(bCol + row0) * K + ko);
        cpasync16(dst + 2 * GARR + row1 * 80 + ch0 * 16, Bl + (size_t)(bCol + row1) * K + ko);
        CP_COMMIT();
    };

    issue(0, 0);
    const int g01 = (lane >> 3) & 1, g23 = lane >> 4, l7 = lane & 7;

    for (int i = 0; i < NIT; i++) {
        if (i + 1 < NIT) { issue(i + 1, (i + 1) & 1); CP_WAIT1(); }
        else             { CP_WAIT0(); }
        __syncthreads();
        const uint32_t aB = sb + (i & 1) * GSTG;
        const uint32_t bB = aB + GARR;
#pragma unroll
        for (int k0 = 0; k0 < 32; k0 += 16) {
            uint32_t bh[4][2], bl[4][2];
#pragma unroll
            for (int p = 0; p < 2; p++) {
                uint32_t bt[4], bt2[4];
                uint32_t bd = bB + (uint32_t)(wn * 32 + p * 16 + l7 + g23 * 8) * 80 + (k0 + g01 * 8) * 2;
                ldm_x4(bt, bd);
                ldm_x4(bt2, bd + GARR);
                bh[2 * p][0] = bt[0]; bh[2 * p][1] = bt[1];
                bh[2 * p + 1][0] = bt[2]; bh[2 * p + 1][1] = bt[3];
                bl[2 * p][0] = bt2[0]; bl[2 * p][1] = bt2[1];
                bl[2 * p + 1][0] = bt2[2]; bl[2 * p + 1][1] = bt2[3];
            }
#pragma unroll
            for (int mt = 0; mt < 4; mt++) {
                uint32_t ah[4];
                uint32_t ad = aB + (uint32_t)(wm * 64 + mt * 16 + l7 + g01 * 8) * 80 + (k0 + g23 * 8) * 2;
                ldm_x4(ah, ad);
#pragma unroll
                for (int nt = 0; nt < 4; nt++) mma16816(acc[mt][nt], ah, bh[nt]);
#pragma unroll
                for (int nt = 0; nt < 4; nt++) mma16816(acc[mt][nt], ah, bl[nt]);
            }
        }
        __syncthreads();
    }

    const int rq = lane >> 2, cq = (lane & 3) * 2;
#pragma unroll
    for (int mt = 0; mt < 4; mt++) {
#pragma unroll
        for (int nt = 0; nt < 4; nt++) {
            int r = bRow + wm * 64 + mt * 16 + rq;
            int c = bCol + wn * 32 + nt * 8 + cq;
            if (OUTMODE == 1) {
                float b0 = bias[c], b1 = bias[c + 1];
                *(float2*)(Cf + (size_t)r * N + c) =
                    make_float2(acc[mt][nt][0] + b0, acc[mt][nt][1] + b1);
                *(float2*)(Cf + (size_t)(r + 8) * N + c) =
                    make_float2(acc[mt][nt][2] + b0, acc[mt][nt][3] + b1);
            } else {
                uint32_t h0, l0, h1, l1;
                split2(acc[mt][nt][0], acc[mt][nt][1], h0, l0);
                split2(acc[mt][nt][2], acc[mt][nt][3], h1, l1);
                *(uint32_t*)(Ch + (size_t)r * N + c) = h0;
                *(uint32_t*)(Cl + (size_t)r * N + c) = l0;
                *(uint32_t*)(Ch + (size_t)(r + 8) * N + c) = h1;
                *(uint32_t*)(Cl + (size_t)(r + 8) * N + c) = l1;
            }
        }
    }
}

// ---------------------------------------------------------------------------
// Tensor-core flash attention (2-pass fp16): Q,P single; K,V split hi/lo.
// 256 thr, 2 CTAs/SM.
// ---------------------------------------------------------------------------
#define AARR 9216
#define ASTG (4 * AARR)                 // Kh, Kl, Vh, Vl
#define ATTN_SMEM (2 * ASTG)            // 73728

__global__ __launch_bounds__(256, 2)
void attn_tc() {
    extern __shared__ char smem[];
    const uint32_t sb = smem_u32(smem);
    const int tid = threadIdx.x, lane = tid & 31, wid = tid >> 5;
    const int b = blockIdx.z, h = blockIdx.y, qb = blockIdx.x;
    const int rq = lane >> 2, cq = (lane & 3) * 2;
    const int l7 = lane & 7, g01 = (lane >> 3) & 1, g23 = lane >> 4;

    uint32_t qh[16];
    {
        const size_t base = (size_t)(b * SS + qb * 128 + wid * 16 + rq) * NQKV + h * DD;
#pragma unroll
        for (int kt = 0; kt < 4; kt++) {
            int c = kt * 16 + cq;
            qh[kt * 4 + 0] = *(const uint32_t*)(g_qkv_h + base + c);
            qh[kt * 4 + 1] = *(const uint32_t*)(g_qkv_h + base + (size_t)8 * NQKV + c);
            qh[kt * 4 + 2] = *(const uint32_t*)(g_qkv_h + base + c + 8);
            qh[kt * 4 + 3] = *(const uint32_t*)(g_qkv_h + base + (size_t)8 * NQKV + c + 8);
        }
    }

    float O[8][4];
#pragma unroll
    for (int i = 0; i < 8; i++)
#pragma unroll
        for (int e = 0; e < 4; e++) O[i][e] = 0.f;
    float m0 = -1e30f, m1 = -1e30f, sl0 = 0.f, sl1 = 0.f;

    const int lrow0 = tid >> 3, lch0 = tid & 7;
    const int lrow1 = (tid + 256) >> 3;
    auto issue = [&](int it, int s) {
        const uint32_t dst = sb + s * ASTG;
        const size_t r0 = (size_t)(b * SS + it * 64 + lrow0) * NQKV;
        const size_t r1 = (size_t)(b * SS + it * 64 + lrow1) * NQKV;
        const int kc = CD + h * DD + lch0 * 8, vc = 2 * CD + h * DD + lch0 * 8;
        cpasync16(dst + 0 * AARR + lrow0 * 144 + lch0 * 16, g_qkv_h + r0 + kc);
        cpasync16(dst + 0 * AARR + lrow1 * 144 + lch0 * 16, g_qkv_h + r1 + kc);
        cpasync16(dst + 1 * AARR + lrow0 * 144 + lch0 * 16, g_qkv_l + r0 + kc);
        cpasync16(dst + 1 * AARR + lrow1 * 144 + lch0 * 16, g_qkv_l + r1 + kc);
        cpasync16(dst + 2 * AARR + lrow0 * 144 + lch0 * 16, g_qkv_h + r0 + vc);
        cpasync16(dst + 2 * AARR + lrow1 * 144 + lch0 * 16, g_qkv_h + r1 + vc);
        cpasync16(dst + 3 * AARR + lrow0 * 144 + lch0 * 16, g_qkv_l + r0 + vc);
        cpasync16(dst + 3 * AARR + lrow1 * 144 + lch0 * 16, g_qkv_l + r1 + vc);
        CP_COMMIT();
    };

    issue(0, 0);
    const int NIT = SS / 64;
    for (int i = 0; i < NIT; i++) {
        if (i + 1 < NIT) { issue(i + 1, (i + 1) & 1); CP_WAIT1(); }
        else             { CP_WAIT0(); }
        __syncthreads();
        const uint32_t kH = sb + (i & 1) * ASTG;
        const uint32_t vH = kH + 2 * AARR;

        float S[8][4];
#pragma unroll
        for (int j = 0; j < 8; j++)
#pragma unroll
            for (int e = 0; e < 4; e++) S[j][e] = 0.f;
#pragma unroll
        for (int kt = 0; kt < 4; kt++) {
#pragma unroll
            for (int p = 0; p < 4; p++) {
                uint32_t kh4[4], kl4[4];
                uint32_t kd = kH + (uint32_t)(p * 16 + l7 + g23 * 8) * 144 + (kt * 16 + g01 * 8) * 2;
                ldm_x4(kh4, kd);
                ldm_x4(kl4, kd + AARR);
                mma16816(S[2 * p],     &qh[kt * 4], &kh4[0]);
                mma16816(S[2 * p + 1], &qh[kt * 4], &kh4[2]);
                mma16816(S[2 * p],     &qh[kt * 4], &kl4[0]);
                mma16816(S[2 * p + 1], &qh[kt * 4], &kl4[2]);
            }
        }

        float nm0 = m0, nm1 = m1;
#pragma unroll
        for (int j = 0; j < 8; j++) {
            S[j][0] *= 0.125f; S[j][1] *= 0.125f; S[j][2] *= 0.125f; S[j][3] *= 0.125f;
            nm0 = fmaxf(nm0, fmaxf(S[j][0], S[j][1]));
            nm1 = fmaxf(nm1, fmaxf(S[j][2], S[j][3]));
        }
        nm0 = fmaxf(nm0, __shfl_xor_sync(0xffffffff, nm0, 1));
        nm0 = fmaxf(nm0, __shfl_xor_sync(0xffffffff, nm0, 2));
        nm1 = fmaxf(nm1, __shfl_xor_sync(0xffffffff, nm1, 1));
        nm1 = fmaxf(nm1, __shfl_xor_sync(0xffffffff, nm1, 2));
        float c0 = __expf(m0 - nm0), c1 = __expf(m1 - nm1);
        m0 = nm0; m1 = nm1;
        float s0 = 0.f, s1 = 0.f;
#pragma unroll
        for (int j = 0; j < 8; j++) {
            S[j][0] = __expf(S[j][0] - m0); S[j][1] = __expf(S[j][1] - m0);
            S[j][2] = __expf(S[j][2] - m1); S[j][3] = __expf(S[j][3] - m1);
            s0 += S[j][0] + S[j][1];
            s1 += S[j][2] + S[j][3];
        }
        s0 += __shfl_xor_sync(0xffffffff, s0, 1);
        s0 += __shfl_xor_sync(0xffffffff, s0, 2);
        s1 += __shfl_xor_sync(0xffffffff, s1, 1);
        s1 += __shfl_xor_sync(0xffffffff, s1, 2);
        sl0 = sl0 * c0 + s0;
        sl1 = sl1 * c1 + s1;
#pragma unroll
        for (int nt = 0; nt < 8; nt++) {
            O[nt][0] *= c0; O[nt][1] *= c0; O[nt][2] *= c1; O[nt][3] *= c1;
        }

#pragma unroll
        for (int kt = 0; kt < 4; kt++) {
            uint32_t ph[4];
            ph[0] = packh(S[2 * kt][0],     S[2 * kt][1]);
            ph[1] = packh(S[2 * kt][2],     S[2 * kt][3]);
            ph[2] = packh(S[2 * kt + 1][0], S[2 * kt + 1][1]);
            ph[3] = packh(S[2 * kt + 1][2], S[2 * kt + 1][3]);
#pragma unroll
            for (int p = 0; p < 4; p++) {
                uint32_t vh4[4], vl4[4];
                uint32_t vd = vH + (uint32_t)(kt * 16 + l7 + g01 * 8) * 144 + (p * 16 + g23 * 8) * 2;
                ldm_x4t(vh4, vd);
                ldm_x4t(vl4, vd + AARR);
                mma16816(O[2 * p],     ph, &vh4[0]);
                mma16816(O[2 * p + 1], ph, &vh4[2]);
                mma16816(O[2 * p],     ph, &vl4[0]);
                mma16816(O[2 * p + 1], ph, &vl4[2]);
            }
        }
        __syncthreads();
    }

    const float i0 = 1.f / sl0, i1 = 1.f / sl1;
    const size_t rb0 = (size_t)(b * SS + qb * 128 + wid * 16 + rq) * CD + h * DD;
    const size_t rb1 = rb0 + (size_t)8 * CD;
#pragma unroll
    for (int nt = 0; nt < 8; nt++) {
        int c = nt * 8 + cq;
        *(uint32_t*)(g_ctx_h + rb0 + c) = packh(O[nt][0] * i0, O[nt][1] * i0);
        *(uint32_t*)(g_ctx_h + rb1 + c) = packh(O[nt][2] * i1, O[nt][3] * i1);
    }
}

// ---------------------------------------------------------------------------
// Launch
// ---------------------------------------------------------------------------
extern "C" void kernel_launch(void* const* d_in, const int* in_sizes, int n_in,
                              void* d_out, int out_size) {
    const float* x  = (const float*)d_in[0];
    const float* Wq = (const float*)d_in[1];
    const float* Wk = (const float*)d_in[2];
    const float* Wv = (const float*)d_in[3];
    const float* Wo = (const float*)d_in[4];
    const float* bo = (const float*)d_in[5];
    const float* Aq = (const float*)d_in[6];
    const float* Bq = (const float*)d_in[7];
    const float* Ak = (const float*)d_in[8];
    const float* Bk = (const float*)d_in[9];
    const float* Av = (const float*)d_in[10];
    const float* Bv = (const float*)d_in[11];
    const float* Ao = (const float*)d_in[12];
    const float* Bo = (const float*)d_in[13];

    static __half *p_xh, *p_Wh, *p_Wl, *p_Woh, *p_Wol, *p_qh, *p_ql, *p_ch;
    static bool init = false;
    if (!init) {
        cudaGetSymbolAddress((void**)&p_xh, g_x_h);
        cudaGetSymbolAddress((void**)&p_Wh, g_W_h);
        cudaGetSymbolAddress((void**)&p_Wl, g_W_l);
        cudaGetSymbolAddress((void**)&p_Woh, g_Wo_h);
        cudaGetSymbolAddress((void**)&p_Wol, g_Wo_l);
        cudaGetSymbolAddress((void**)&p_qh, g_qkv_h);
        cudaGetSymbolAddress((void**)&p_ql, g_qkv_l);
        cudaGetSymbolAddress((void**)&p_ch, g_ctx_h);
        cudaFuncSetAttribute(gemm_tc<0>, cudaFuncAttributeMaxDynamicSharedMemorySize, GEMM_SMEM);
        cudaFuncSetAttribute(gemm_tc<1>, cudaFuncAttributeMaxDynamicSharedMemorySize, GEMM_SMEM);
        cudaFuncSetAttribute(attn_tc, cudaFuncAttributeMaxDynamicSharedMemorySize, ATTN_SMEM);
        init = true;
    }

    fold_qkv_kernel<<<(NQKV * CD + 255) / 256, 256>>>(Wq, Wk, Wv, Aq, Bq, Ak, Bk, Av, Bv);
    fold_o_kernel<<<(CD * CD + 255) / 256, 256>>>(Wo, Ao, Bo);
    convert_x_kernel<<<(MM * CD + 255) / 256, 256>>>(x);

    // QKV projection: x (single) @ W (split) -> qkv hi/lo
    gemm_tc<0><<<dim3(NQKV / 128, MM / 128), 256, GEMM_SMEM>>>(
        p_xh, p_Wh, p_Wl, nullptr, p_qh, p_ql, CD, NQKV, nullptr);

    attn_tc<<<dim3(SS / 128, HH, BB), 256, ATTN_SMEM>>>();

    // O projection: ctx (single) @ Wo (split) + bias -> fp32 out
    gemm_tc<1><<<dim3(CD / 128, MM / 128), 256, GEMM_SMEM>>>(
        p_ch, p_Woh, p_Wol, (float*)d_out, nullptr, nullptr, CD, CD, bo);
}

// round 9
// speedup vs baseline: 1.7215x; 1.0898x over previous
#include <cuda_runtime.h>
#include <cuda_fp16.h>
#include <cstdint>

#define CD 1280
#define RD 4
#define BB 2
#define SS 2048
#define MM 4096
#define HH 20
#define DD 64
#define NQKV 3840

// ---------------- device scratch (fp16; weights/K split hi+lo) ----------------
__device__ __half g_x_h[MM * CD];
__device__ __half g_W_h[NQKV * CD],  g_W_l[NQKV * CD];
__device__ __half g_Wo_h[CD * CD],   g_Wo_l[CD * CD];
__device__ __half g_qkv_h[MM * NQKV], g_qkv_l[MM * NQKV];
__device__ __half g_ctx_h[MM * CD];

// ---------------- helpers ----------------
__device__ __forceinline__ uint32_t smem_u32(const void* p) {
    uint32_t a;
    asm("{ .reg .u64 t; cvta.to.shared.u64 t, %1; cvt.u32.u64 %0, t; }" : "=r"(a) : "l"(p));
    return a;
}
__device__ __forceinline__ uint32_t packh(float lo, float hi) {
    uint32_t r;
    asm("cvt.rn.f16x2.f32 %0, %1, %2;" : "=r"(r) : "f"(hi), "f"(lo));
    return r;
}
__device__ __forceinline__ void split2(float x, float y, uint32_t& h, uint32_t& l) {
    __half hx = __float2half_rn(x), hy = __float2half_rn(y);
    h = ((uint32_t)__half_as_ushort(hy) << 16) | (uint32_t)__half_as_ushort(hx);
    l = packh(x - __half2float(hx), y - __half2float(hy));
}

__device__ __forceinline__ void mma16816(float* d, const uint32_t* a, const uint32_t* b) {
    asm volatile(
        "mma.sync.aligned.m16n8k16.row.col.f32.f16.f16.f32 "
        "{%0,%1,%2,%3}, {%4,%5,%6,%7}, {%8,%9}, {%0,%1,%2,%3};"
        : "+f"(d[0]), "+f"(d[1]), "+f"(d[2]), "+f"(d[3])
        : "r"(a[0]), "r"(a[1]), "r"(a[2]), "r"(a[3]), "r"(b[0]), "r"(b[1]));
}
__device__ __forceinline__ void ldm_x4(uint32_t* r, uint32_t addr) {
    asm volatile("ldmatrix.sync.aligned.m8n8.x4.shared.b16 {%0,%1,%2,%3}, [%4];"
                 : "=r"(r[0]), "=r"(r[1]), "=r"(r[2]), "=r"(r[3]) : "r"(addr));
}
__device__ __forceinline__ void ldm_x4t(uint32_t* r, uint32_t addr) {
    asm volatile("ldmatrix.sync.aligned.m8n8.x4.trans.shared.b16 {%0,%1,%2,%3}, [%4];"
                 : "=r"(r[0]), "=r"(r[1]), "=r"(r[2]), "=r"(r[3]) : "r"(addr));
}
__device__ __forceinline__ void cpasync16(uint32_t dst, const void* src) {
    asm volatile("cp.async.cg.shared.global [%0], [%1], 16;" :: "r"(dst), "l"(src));
}
#define CP_COMMIT() asm volatile("cp.async.commit_group;" ::: "memory")
#define CP_WAIT1()  asm volatile("cp.async.wait_group 1;" ::: "memory")
#define CP_WAIT0()  asm volatile("cp.async.wait_group 0;" ::: "memory")

// ---------------------------------------------------------------------------
// Merged prep: fold LoRA into weights (hi/lo) + convert x to fp16, one launch.
// Linear-index partition: [0, NQKV*CD) fold qkv, [.., +CD*CD) fold o,
// [.., +MM*CD) convert x.
// ---------------------------------------------------------------------------
#define PREP_N1 (NQKV * CD)
#define PREP_N2 (PREP_N1 + CD * CD)
#define PREP_N3 (PREP_N2 + MM * CD)

__global__ void prep_kernel(const float* __restrict__ x,
                            const float* __restrict__ Wq, const float* __restrict__ Wk,
                            const float* __restrict__ Wv, const float* __restrict__ Wo,
                            const float* __restrict__ Aq, const float* __restrict__ Bq,
                            const float* __restrict__ Ak, const float* __restrict__ Bk,
                            const float* __restrict__ Av, const float* __restrict__ Bv,
                            const float* __restrict__ Ao, const float* __restrict__ Bo) {
    int idx = blockIdx.x * blockDim.x + threadIdx.x;
    if (idx < PREP_N1) {
        int n = idx / CD;
        int c = idx - n * CD;
        const float *W, *A, *B;
        int j;
        if (n < CD)          { W = Wq; A = Aq; B = Bq; j = n; }
        else if (n < 2 * CD) { W = Wk; A = Ak; B = Bk; j = n - CD; }
        else                 { W = Wv; A = Av; B = Bv; j = n - 2 * CD; }
        float acc = W[j * CD + c];
#pragma unroll
        for (int r = 0; r < RD; r++)
            acc = fmaf(B[j * RD + r], A[r * CD + c], acc);
        __half h = __float2half_rn(acc);
        g_W_h[idx] = h;
        g_W_l[idx] = __float2half_rn(acc - __half2float(h));
    } else if (idx < PREP_N2) {
        int i2 = idx - PREP_N1;
        int j = i2 / CD;
        int c = i2 - j * CD;
        float acc = Wo[i2];
#pragma unroll
        for (int r = 0; r < RD; r++)
            acc = fmaf(Bo[j * RD + r], Ao[r * CD + c], acc);
        __half h = __float2half_rn(acc);
        g_Wo_h[i2] = h;
        g_Wo_l[i2] = __float2half_rn(acc - __half2float(h));
    } else if (idx < PREP_N3) {
        int i3 = idx - PREP_N2;
        g_x_h[i3] = __float2half_rn(x[i3]);
    }
}

// ---------------------------------------------------------------------------
// HMMA GEMM (2-pass fp16):  C[m][n] = sum_k A[m][k]*(Bh+Bl)[n][k]
// A single fp16; B split hi/lo. BM=128, BN=128, BK=32, 256 thr, 2 CTAs/SM.
// ---------------------------------------------------------------------------
#define GARR 10240
#define GSTG (3 * GARR)                 // A, Bh, Bl
#define GEMM_SMEM (2 * GSTG)            // 61440

template <int OUTMODE>
__global__ __launch_bounds__(256, 2)
void gemm_tc(const __half* __restrict__ Ah,
             const __half* __restrict__ Bh, const __half* __restrict__ Bl,
             float* __restrict__ Cf, __half* __restrict__ Ch, __half* __restrict__ Cl,
             int K, int N, const float* __restrict__ bias) {
    extern __shared__ char smem[];
    const uint32_t sb = smem_u32(smem);
    const int tid = threadIdx.x, lane = tid & 31, wid = tid >> 5;
    const int wm = wid & 1, wn = wid >> 1;
    const int bRow = blockIdx.y * 128, bCol = blockIdx.x * 128;

    float acc[4][4][4];
#pragma unroll
    for (int i = 0; i < 4; i++)
#pragma unroll
        for (int j = 0; j < 4; j++)
#pragma unroll
            for (int e = 0; e < 4; e++) acc[i][j][e] = 0.f;

    const int NIT = K / 32;
    const int row0 = tid >> 2, ch0 = tid & 3;
    const int row1 = (tid + 256) >> 2;

    auto issue = [&](int it, int s) {
        const uint32_t dst = sb + s * GSTG;
        const size_t ko = (size_t)it * 32 + ch0 * 8;
        cpasync16(dst + 0 * GARR + row0 * 80 + ch0 * 16, Ah + (size_t)(bRow + row0) * K + ko);
        cpasync16(dst + 0 * GARR + row1 * 80 + ch0 * 16, Ah + (size_t)(bRow + row1) * K + ko);
        cpasync16(dst + 1 * GARR + row0 * 80 + ch0 * 16, Bh + (size_t)(bCol + row0) * K + ko);
        cpasync16(dst + 1 * GARR + row1 * 80 + ch0 * 16, Bh + (size_t)(bCol + row1) * K + ko);
        cpasync16(dst + 2 * GARR + row0 * 80 + ch0 * 16, Bl + (size_t)(bCol + row0) * K + ko);
        cpasync16(dst + 2 * GARR + row1 * 80 + ch0 * 16, Bl + (size_t)(bCol + row1) * K + ko);
        CP_COMMIT();
    };

    issue(0, 0);
    const int g01 = (lane >> 3) & 1, g23 = lane >> 4, l7 = lane & 7;

    for (int i = 0; i < NIT; i++) {
        if (i + 1 < NIT) { issue(i + 1, (i + 1) & 1); CP_WAIT1(); }
        else             { CP_WAIT0(); }
        __syncthreads();
        const uint32_t aB = sb + (i & 1) * GSTG;
        const uint32_t bB = aB + GARR;
#pragma unroll
        for (int k0 = 0; k0 < 32; k0 += 16) {
            uint32_t bh[4][2], bl[4][2];
#pragma unroll
            for (int p = 0; p < 2; p++) {
                uint32_t bt[4], bt2[4];
                uint32_t bd = bB + (uint32_t)(wn * 32 + p * 16 + l7 + g23 * 8) * 80 + (k0 + g01 * 8) * 2;
                ldm_x4(bt, bd);
                ldm_x4(bt2, bd + GARR);
                bh[2 * p][0] = bt[0]; bh[2 * p][1] = bt[1];
                bh[2 * p + 1][0] = bt[2]; bh[2 * p + 1][1] = bt[3];
                bl[2 * p][0] = bt2[0]; bl[2 * p][1] = bt2[1];
                bl[2 * p + 1][0] = bt2[2]; bl[2 * p + 1][1] = bt2[3];
            }
#pragma unroll
            for (int mt = 0; mt < 4; mt++) {
                uint32_t ah[4];
                uint32_t ad = aB + (uint32_t)(wm * 64 + mt * 16 + l7 + g01 * 8) * 80 + (k0 + g23 * 8) * 2;
                ldm_x4(ah, ad);
#pragma unroll
                for (int nt = 0; nt < 4; nt++) mma16816(acc[mt][nt], ah, bh[nt]);
#pragma unroll
                for (int nt = 0; nt < 4; nt++) mma16816(acc[mt][nt], ah, bl[nt]);
            }
        }
        __syncthreads();
    }

    const int rq = lane >> 2, cq = (lane & 3) * 2;
#pragma unroll
    for (int mt = 0; mt < 4; mt++) {
#pragma unroll
        for (int nt = 0; nt < 4; nt++) {
            int r = bRow + wm * 64 + mt * 16 + rq;
            int c = bCol + wn * 32 + nt * 8 + cq;
            if (OUTMODE == 1) {
                float b0 = bias[c], b1 = bias[c + 1];
                *(float2*)(Cf + (size_t)r * N + c) =
                    make_float2(acc[mt][nt][0] + b0, acc[mt][nt][1] + b1);
                *(float2*)(Cf + (size_t)(r + 8) * N + c) =
                    make_float2(acc[mt][nt][2] + b0, acc[mt][nt][3] + b1);
            } else {
                uint32_t h0, l0, h1, l1;
                split2(acc[mt][nt][0], acc[mt][nt][1], h0, l0);
                split2(acc[mt][nt][2], acc[mt][nt][3], h1, l1);
                *(uint32_t*)(Ch + (size_t)r * N + c) = h0;
                *(uint32_t*)(Cl + (size_t)r * N + c) = l0;
                *(uint32_t*)(Ch + (size_t)(r + 8) * N + c) = h1;
                *(uint32_t*)(Cl + (size_t)(r + 8) * N + c) = l1;
            }
        }
    }
}

// ---------------------------------------------------------------------------
// Tensor-core flash attention: Q,P single fp16; K split hi/lo; V single fp16.
// QK = 2-pass, PV = 1-pass. 256 thr, 2 CTAs/SM.
// ---------------------------------------------------------------------------
#define AARR 9216
#define ASTG (3 * AARR)                 // Kh, Kl, Vh
#define ATTN_SMEM (2 * ASTG)            // 55296

__global__ __launch_bounds__(256, 2)
void attn_tc() {
    extern __shared__ char smem[];
    const uint32_t sb = smem_u32(smem);
    const int tid = threadIdx.x, lane = tid & 31, wid = tid >> 5;
    const int b = blockIdx.z, h = blockIdx.y, qb = blockIdx.x;
    const int rq = lane >> 2, cq = (lane & 3) * 2;
    const int l7 = lane & 7, g01 = (lane >> 3) & 1, g23 = lane >> 4;

    uint32_t qh[16];
    {
        const size_t base = (size_t)(b * SS + qb * 128 + wid * 16 + rq) * NQKV + h * DD;
#pragma unroll
        for (int kt = 0; kt < 4; kt++) {
            int c = kt * 16 + cq;
            qh[kt * 4 + 0] = *(const uint32_t*)(g_qkv_h + base + c);
            qh[kt * 4 + 1] = *(const uint32_t*)(g_qkv_h + base + (size_t)8 * NQKV + c);
            qh[kt * 4 + 2] = *(const uint32_t*)(g_qkv_h + base + c + 8);
            qh[kt * 4 + 3] = *(const uint32_t*)(g_qkv_h + base + (size_t)8 * NQKV + c + 8);
        }
    }

    float O[8][4];
#pragma unroll
    for (int i = 0; i < 8; i++)
#pragma unroll
        for (int e = 0; e < 4; e++) O[i][e] = 0.f;
    float m0 = -1e30f, m1 = -1e30f, sl0 = 0.f, sl1 = 0.f;

    const int lrow0 = tid >> 3, lch0 = tid & 7;
    const int lrow1 = (tid + 256) >> 3;
    auto issue = [&](int it, int s) {
        const uint32_t dst = sb + s * ASTG;
        const size_t r0 = (size_t)(b * SS + it * 64 + lrow0) * NQKV;
        const size_t r1 = (size_t)(b * SS + it * 64 + lrow1) * NQKV;
        const int kc = CD + h * DD + lch0 * 8, vc = 2 * CD + h * DD + lch0 * 8;
        cpasync16(dst + 0 * AARR + lrow0 * 144 + lch0 * 16, g_qkv_h + r0 + kc);
        cpasync16(dst + 0 * AARR + lrow1 * 144 + lch0 * 16, g_qkv_h + r1 + kc);
        cpasync16(dst + 1 * AARR + lrow0 * 144 + lch0 * 16, g_qkv_l + r0 + kc);
        cpasync16(dst + 1 * AARR + lrow1 * 144 + lch0 * 16, g_qkv_l + r1 + kc);
        cpasync16(dst + 2 * AARR + lrow0 * 144 + lch0 * 16, g_qkv_h + r0 + vc);
        cpasync16(dst + 2 * AARR + lrow1 * 144 + lch0 * 16, g_qkv_h + r1 + vc);
        CP_COMMIT();
    };

    issue(0, 0);
    const int NIT = SS / 64;
    for (int i = 0; i < NIT; i++) {
        if (i + 1 < NIT) { issue(i + 1, (i + 1) & 1); CP_WAIT1(); }
        else             { CP_WAIT0(); }
        __syncthreads();
        const uint32_t kH = sb + (i & 1) * ASTG;
        const uint32_t vH = kH + 2 * AARR;

        float S[8][4];
#pragma unroll
        for (int j = 0; j < 8; j++)
#pragma unroll
            for (int e = 0; e < 4; e++) S[j][e] = 0.f;
#pragma unroll
        for (int kt = 0; kt < 4; kt++) {
#pragma unroll
            for (int p = 0; p < 4; p++) {
                uint32_t kh4[4], kl4[4];
                uint32_t kd = kH + (uint32_t)(p * 16 + l7 + g23 * 8) * 144 + (kt * 16 + g01 * 8) * 2;
                ldm_x4(kh4, kd);
                ldm_x4(kl4, kd + AARR);
                mma16816(S[2 * p],     &qh[kt * 4], &kh4[0]);
                mma16816(S[2 * p + 1], &qh[kt * 4], &kh4[2]);
                mma16816(S[2 * p],     &qh[kt * 4], &kl4[0]);
                mma16816(S[2 * p + 1], &qh[kt * 4], &kl4[2]);
            }
        }

        float nm0 = m0, nm1 = m1;
#pragma unroll
        for (int j = 0; j < 8; j++) {
            S[j][0] *= 0.125f; S[j][1] *= 0.125f; S[j][2] *= 0.125f; S[j][3] *= 0.125f;
            nm0 = fmaxf(nm0, fmaxf(S[j][0], S[j][1]));
            nm1 = fmaxf(nm1, fmaxf(S[j][2], S[j][3]));
        }
        nm0 = fmaxf(nm0, __shfl_xor_sync(0xffffffff, nm0, 1));
        nm0 = fmaxf(nm0, __shfl_xor_sync(0xffffffff, nm0, 2));
        nm1 = fmaxf(nm1, __shfl_xor_sync(0xffffffff, nm1, 1));
        nm1 = fmaxf(nm1, __shfl_xor_sync(0xffffffff, nm1, 2));
        float c0 = __expf(m0 - nm0), c1 = __expf(m1 - nm1);
        m0 = nm0; m1 = nm1;
        float s0 = 0.f, s1 = 0.f;
#pragma unroll
        for (int j = 0; j < 8; j++) {
            S[j][0] = __expf(S[j][0] - m0); S[j][1] = __expf(S[j][1] - m0);
            S[j][2] = __expf(S[j][2] - m1); S[j][3] = __expf(S[j][3] - m1);
            s0 += S[j][0] + S[j][1];
            s1 += S[j][2] + S[j][3];
        }
        s0 += __shfl_xor_sync(0xffffffff, s0, 1);
        s0 += __shfl_xor_sync(0xffffffff, s0, 2);
        s1 += __shfl_xor_sync(0xffffffff, s1, 1);
        s1 += __shfl_xor_sync(0xffffffff, s1, 2);
        sl0 = sl0 * c0 + s0;
        sl1 = sl1 * c1 + s1;
#pragma unroll
        for (int nt = 0; nt < 8; nt++) {
            O[nt][0] *= c0; O[nt][1] *= c0; O[nt][2] *= c1; O[nt][3] *= c1;
        }

#pragma unroll
        for (int kt = 0; kt < 4; kt++) {
            uint32_t ph[4];
            ph[0] = packh(S[2 * kt][0],     S[2 * kt][1]);
            ph[1] = packh(S[2 * kt][2],     S[2 * kt][3]);
            ph[2] = packh(S[2 * kt + 1][0], S[2 * kt + 1][1]);
            ph[3] = packh(S[2 * kt + 1][2], S[2 * kt + 1][3]);
#pragma unroll
            for (int p = 0; p < 4; p++) {
                uint32_t vh4[4];
                uint32_t vd = vH + (uint32_t)(kt * 16 + l7 + g01 * 8) * 144 + (p * 16 + g23 * 8) * 2;
                ldm_x4t(vh4, vd);
                mma16816(O[2 * p],     ph, &vh4[0]);
                mma16816(O[2 * p + 1], ph, &vh4[2]);
            }
        }
        __syncthreads();
    }

    const float i0 = 1.f / sl0, i1 = 1.f / sl1;
    const size_t rb0 = (size_t)(b * SS + qb * 128 + wid * 16 + rq) * CD + h * DD;
    const size_t rb1 = rb0 + (size_t)8 * CD;
#pragma unroll
    for (int nt = 0; nt < 8; nt++) {
        int c = nt * 8 + cq;
        *(uint32_t*)(g_ctx_h + rb0 + c) = packh(O[nt][0] * i0, O[nt][1] * i0);
        *(uint32_t*)(g_ctx_h + rb1 + c) = packh(O[nt][2] * i1, O[nt][3] * i1);
    }
}

// ---------------------------------------------------------------------------
// Launch
// ---------------------------------------------------------------------------
extern "C" void kernel_launch(void* const* d_in, const int* in_sizes, int n_in,
                              void* d_out, int out_size) {
    const float* x  = (const float*)d_in[0];
    const float* Wq = (const float*)d_in[1];
    const float* Wk = (const float*)d_in[2];
    const float* Wv = (const float*)d_in[3];
    const float* Wo = (const float*)d_in[4];
    const float* bo = (const float*)d_in[5];
    const float* Aq = (const float*)d_in[6];
    const float* Bq = (const float*)d_in[7];
    const float* Ak = (const float*)d_in[8];
    const float* Bk = (const float*)d_in[9];
    const float* Av = (const float*)d_in[10];
    const float* Bv = (const float*)d_in[11];
    const float* Ao = (const float*)d_in[12];
    const float* Bo = (const float*)d_in[13];

    static __half *p_xh, *p_Wh, *p_Wl, *p_Woh, *p_Wol, *p_qh, *p_ql, *p_ch;
    static bool init = false;
    if (!init) {
        cudaGetSymbolAddress((void**)&p_xh, g_x_h);
        cudaGetSymbolAddress((void**)&p_Wh, g_W_h);
        cudaGetSymbolAddress((void**)&p_Wl, g_W_l);
        cudaGetSymbolAddress((void**)&p_Woh, g_Wo_h);
        cudaGetSymbolAddress((void**)&p_Wol, g_Wo_l);
        cudaGetSymbolAddress((void**)&p_qh, g_qkv_h);
        cudaGetSymbolAddress((void**)&p_ql, g_qkv_l);
        cudaGetSymbolAddress((void**)&p_ch, g_ctx_h);
        cudaFuncSetAttribute(gemm_tc<0>, cudaFuncAttributeMaxDynamicSharedMemorySize, GEMM_SMEM);
        cudaFuncSetAttribute(gemm_tc<1>, cudaFuncAttributeMaxDynamicSharedMemorySize, GEMM_SMEM);
        cudaFuncSetAttribute(attn_tc, cudaFuncAttributeMaxDynamicSharedMemorySize, ATTN_SMEM);
        init = true;
    }

    // 1) merged prep: fold LoRA + split weights + convert x (one launch)
    prep_kernel<<<PREP_N3 / 256, 256>>>(x, Wq, Wk, Wv, Wo,
                                        Aq, Bq, Ak, Bk, Av, Bv, Ao, Bo);

    // 2) QKV projection: x (single) @ W (split) -> qkv hi/lo
    gemm_tc<0><<<dim3(NQKV / 128, MM / 128), 256, GEMM_SMEM>>>(
        p_xh, p_Wh, p_Wl, nullptr, p_qh, p_ql, CD, NQKV, nullptr);

    // 3) attention (QK 2-pass, PV 1-pass) -> ctx fp16
    attn_tc<<<dim3(SS / 128, HH, BB), 256, ATTN_SMEM>>>();

    // 4) O projection: ctx (single) @ Wo (split) + bias -> fp32 out
    gemm_tc<1><<<dim3(CD / 128, MM / 128), 256, GEMM_SMEM>>>(
        p_ch, p_Woh, p_Wol, (float*)d_out, nullptr, nullptr, CD, CD, bo);
}